// round 3
// baseline (speedup 1.0000x reference)
#include <cuda_runtime.h>
#include <math.h>

// Hyp-MLR: N=4096, C=256, D=128, CURV=1
// out[n,c] = 2*||a_c|| * asinh(dot * lam); everything reduces to scalars from
// the two GEMMs X.P^T, X.A^T plus per-row/per-class stats (x2, p2, a2, p.a).
// GEMMs run as K-packed fma.rn.f32x2 (2 k-steps per instruction); stats are
// computed once per block in a shuffle-reduce preamble.

#define N_TOT 4096
#define C_TOT 256
#define D_TOT 128
#define BN 64
#define BC 64
#define KP 16              // k-PAIRS per tile (= 32 scalar k)
#define XSTR (BN + 2)      // float2 row stride (528B: 16B-aligned)
#define CSTR (BC + 2)

typedef unsigned long long u64t;

__device__ __forceinline__ u64t fma2(u64t a, u64t b, u64t c) {
    u64t d;
    asm("fma.rn.f32x2 %0, %1, %2, %3;" : "=l"(d) : "l"(a), "l"(b), "l"(c));
    return d;
}
__device__ __forceinline__ float hsum2(u64t v) {
    float lo, hi;
    asm("mov.b64 {%0, %1}, %2;" : "=f"(lo), "=f"(hi) : "l"(v));
    return lo + hi;
}
__device__ __forceinline__ void lds2(u64t& a, u64t& b, unsigned addr) {
    asm volatile("ld.shared.v2.u64 {%0, %1}, [%2];"
                 : "=l"(a), "=l"(b) : "r"(addr));
}

__global__ __launch_bounds__(256, 2) void hyp_mlr_kernel(
    const float* __restrict__ X,   // (N, D)
    const float* __restrict__ A,   // (C, D)
    const float* __restrict__ P,   // (C, D)
    float* __restrict__ out)       // (N, C)
{
    __shared__ float2 Xs[KP][XSTR];
    __shared__ float2 Ps[KP][CSTR];
    __shared__ float2 As[KP][CSTR];
    __shared__ float x2s[BN];
    __shared__ float p2s[BC];
    __shared__ float na2s[BC];
    __shared__ float pas[BC];

    const int tid = threadIdx.x;
    const int lid = tid & 31;
    const int wid = tid >> 5;
    const int tx  = tid & 15;   // c dim
    const int ty  = tid >> 4;   // n dim
    const int n0  = blockIdx.y * BN;
    const int c0  = blockIdx.x * BC;

    // ---- Stats preamble: warps 0-3 do the 64 n-rows, warps 4-7 the 64 c-rows.
    if (wid < 4) {
        #pragma unroll 4
        for (int j = 0; j < 16; j++) {
            int row = wid * 16 + j;
            float4 v = *(const float4*)&X[(size_t)(n0 + row) * D_TOT + lid * 4];
            float s = v.x * v.x + v.y * v.y + v.z * v.z + v.w * v.w;
            #pragma unroll
            for (int o = 16; o > 0; o >>= 1) s += __shfl_xor_sync(~0u, s, o);
            if (lid == 0) x2s[row] = s;
        }
    } else {
        #pragma unroll 4
        for (int j = 0; j < 16; j++) {
            int row = (wid - 4) * 16 + j;
            float4 p = *(const float4*)&P[(size_t)(c0 + row) * D_TOT + lid * 4];
            float4 a = *(const float4*)&A[(size_t)(c0 + row) * D_TOT + lid * 4];
            float sp  = p.x * p.x + p.y * p.y + p.z * p.z + p.w * p.w;
            float sa  = a.x * a.x + a.y * a.y + a.z * a.z + a.w * a.w;
            float spa = p.x * a.x + p.y * a.y + p.z * a.z + p.w * a.w;
            #pragma unroll
            for (int o = 16; o > 0; o >>= 1) {
                sp  += __shfl_xor_sync(~0u, sp,  o);
                sa  += __shfl_xor_sync(~0u, sa,  o);
                spa += __shfl_xor_sync(~0u, spa, o);
            }
            if (lid == 0) { p2s[row] = sp; na2s[row] = sa; pas[row] = spa; }
        }
    }
    // ordering vs epilogue reads is covered by the __syncthreads in the k0 loop

    const unsigned xb = (unsigned)__cvta_generic_to_shared(Xs);
    const unsigned pb = (unsigned)__cvta_generic_to_shared(Ps);
    const unsigned ab = (unsigned)__cvta_generic_to_shared(As);

    u64t axp[4][4] = {};   // packed (even-k, odd-k) partial sums of x.p
    u64t axa[4][4] = {};   // packed partial sums of x.a

    for (int k0 = 0; k0 < D_TOT; k0 += 2 * KP) {
        // Tile fill: 1024 float2 per array, 4 per thread, coalesced on k.
        #pragma unroll
        for (int r = 0; r < 4; r++) {
            int idx = tid + r * 256;
            int kk  = idx & 15;
            int row = idx >> 4;
            Xs[kk][row] = *(const float2*)&X[(size_t)(n0 + row) * D_TOT + k0 + 2 * kk];
            Ps[kk][row] = *(const float2*)&P[(size_t)(c0 + row) * D_TOT + k0 + 2 * kk];
            As[kk][row] = *(const float2*)&A[(size_t)(c0 + row) * D_TOT + k0 + 2 * kk];
        }
        __syncthreads();

        #pragma unroll
        for (int k = 0; k < KP; k++) {
            u64t xk[4], pk[4], ak[4];
            unsigned xo = xb + k * (XSTR * 8) + ty * 32;
            unsigned co = k * (CSTR * 8) + tx * 32;
            lds2(xk[0], xk[1], xo);
            lds2(xk[2], xk[3], xo + 16);
            lds2(pk[0], pk[1], pb + co);
            lds2(pk[2], pk[3], pb + co + 16);
            lds2(ak[0], ak[1], ab + co);
            lds2(ak[2], ak[3], ab + co + 16);
            #pragma unroll
            for (int i = 0; i < 4; i++)
                #pragma unroll
                for (int j = 0; j < 4; j++) {
                    axp[i][j] = fma2(xk[i], pk[j], axp[i][j]);
                    axa[i][j] = fma2(xk[i], ak[j], axa[i][j]);
                }
        }
        __syncthreads();
    }

    // ---- Epilogue: scalar hyperbolic math per (n,c), vectorized store.
    float4 xx = *(const float4*)&x2s[ty * 4];
    float4 pp = *(const float4*)&p2s[tx * 4];
    float4 aa = *(const float4*)&na2s[tx * 4];
    float4 pv = *(const float4*)&pas[tx * 4];
    float x2v[4] = {xx.x, xx.y, xx.z, xx.w};
    float p2v[4] = {pp.x, pp.y, pp.z, pp.w};
    float a2v[4] = {aa.x, aa.y, aa.z, aa.w};
    float pav[4] = {pv.x, pv.y, pv.z, pv.w};

    #pragma unroll
    for (int i = 0; i < 4; i++) {
        const int n = n0 + ty * 4 + i;
        float res[4];
        #pragma unroll
        for (int j = 0; j < 4; j++) {
            float xy    = -hsum2(axp[i][j]);             // mp . x
            float xa    =  hsum2(axa[i][j]);             // x . a
            float x2    = x2v[i];
            float p2    = p2v[j];
            float alpha = 1.0f + 2.0f * xy + x2;
            float beta  = 1.0f - p2;
            float den   = 1.0f + 2.0f * xy + p2 * x2;
            float inv_den = 1.0f / den;
            float r2 = (alpha * alpha * p2
                        + 2.0f * alpha * beta * xy
                        + beta * beta * x2) * inv_den * inv_den;
            float lam = 2.0f / (1.0f - r2);
            float na  = sqrtf(a2v[j]);
            float inv_na = 1.0f / fmaxf(na, 1e-12f);
            float dot = (beta * xa - alpha * pav[j]) * inv_den * inv_na;
            res[j] = 2.0f * na * asinhf(dot * lam);
        }
        float4 o = {res[0], res[1], res[2], res[3]};
        *(float4*)&out[(size_t)n * C_TOT + c0 + tx * 4] = o;
    }
}

extern "C" void kernel_launch(void* const* d_in, const int* in_sizes, int n_in,
                              void* d_out, int out_size) {
    const float* X = (const float*)d_in[0];   // output_before (N, D)
    const float* A = (const float*)d_in[1];   // a_mlr (C, D)
    const float* P = (const float*)d_in[2];   // p_mlr (C, D)
    float* out = (float*)d_out;               // (N, C)

    dim3 grid(C_TOT / BC, N_TOT / BN);        // (4, 64) = 256 blocks
    hyp_mlr_kernel<<<grid, 256>>>(X, A, P, out);
}

// round 4
// speedup vs baseline: 1.0145x; 1.0145x over previous
#include <cuda_runtime.h>
#include <math.h>

// Hyp-MLR: N=4096, C=256, D=128, CURV=1
// out[n,c] = 2*||a_c|| * asinh(dot*lam); reduces to two GEMMs (X.P^T, X.A^T)
// + per-row/per-class stats. GEMM via packed fma.rn.f32x2 (2 k/instr) fed by
// compiler-scheduled LDS.128; epilogue fully fused with approx rcp/sqrt/lg2.

#define N_TOT 4096
#define C_TOT 256
#define D_TOT 128
#define BN 64
#define BC 64
#define KP 16              // k-pairs per tile (= 32 scalar k)
#define XSTR (BN + 2)      // float2 row stride -> 528B rows, 16B aligned
#define CSTR (BC + 2)
#define LN2F 0.69314718055994530942f

typedef unsigned long long u64t;

__device__ __forceinline__ u64t fma2(u64t a, u64t b, u64t c) {
    u64t d;
    asm("fma.rn.f32x2 %0, %1, %2, %3;" : "=l"(d) : "l"(a), "l"(b), "l"(c));
    return d;
}
__device__ __forceinline__ float hsum2(u64t v) {
    float lo, hi;
    asm("mov.b64 {%0, %1}, %2;" : "=f"(lo), "=f"(hi) : "l"(v));
    return lo + hi;
}
__device__ __forceinline__ float fast_rcp(float x) {
    float y; asm("rcp.approx.f32 %0, %1;" : "=f"(y) : "f"(x)); return y;
}
__device__ __forceinline__ float fast_sqrt(float x) {
    float y; asm("sqrt.approx.f32 %0, %1;" : "=f"(y) : "f"(x)); return y;
}
__device__ __forceinline__ float fast_lg2(float x) {
    float y; asm("lg2.approx.f32 %0, %1;" : "=f"(y) : "f"(x)); return y;
}

__global__ __launch_bounds__(256, 2) void hyp_mlr_kernel(
    const float* __restrict__ X,   // (N, D)
    const float* __restrict__ A,   // (C, D)
    const float* __restrict__ P,   // (C, D)
    float* __restrict__ out)       // (N, C)
{
    __shared__ float2 Xs[KP][XSTR];
    __shared__ float2 Ps[KP][CSTR];
    __shared__ float2 As[KP][CSTR];
    __shared__ float x2s[BN];                       // ||x||^2 per row
    __shared__ float p2s[BC], pas[BC];              // ||p||^2, p.a per class
    __shared__ float inas[BC], w2s[BC];             // 1/||a||, 2*||a||*ln2

    const int tid = threadIdx.x;
    const int lid = tid & 31;
    const int wid = tid >> 5;
    const int tx  = tid & 15;   // c dim
    const int ty  = tid >> 4;   // n dim
    const int n0  = blockIdx.y * BN;
    const int c0  = blockIdx.x * BC;

    // ---- Stats preamble: warps 0-3 -> 64 n-rows; warps 4-7 -> 64 c-rows.
    if (wid < 4) {
        #pragma unroll 4
        for (int j = 0; j < 16; j++) {
            int row = wid * 16 + j;
            float4 v = *(const float4*)&X[(size_t)(n0 + row) * D_TOT + lid * 4];
            float s = v.x * v.x + v.y * v.y + v.z * v.z + v.w * v.w;
            #pragma unroll
            for (int o = 16; o > 0; o >>= 1) s += __shfl_xor_sync(~0u, s, o);
            if (lid == 0) x2s[row] = s;
        }
    } else {
        #pragma unroll 4
        for (int j = 0; j < 16; j++) {
            int row = (wid - 4) * 16 + j;
            float4 p = *(const float4*)&P[(size_t)(c0 + row) * D_TOT + lid * 4];
            float4 a = *(const float4*)&A[(size_t)(c0 + row) * D_TOT + lid * 4];
            float sp  = p.x * p.x + p.y * p.y + p.z * p.z + p.w * p.w;
            float sa  = a.x * a.x + a.y * a.y + a.z * a.z + a.w * a.w;
            float spa = p.x * a.x + p.y * a.y + p.z * a.z + p.w * a.w;
            #pragma unroll
            for (int o = 16; o > 0; o >>= 1) {
                sp  += __shfl_xor_sync(~0u, sp,  o);
                sa  += __shfl_xor_sync(~0u, sa,  o);
                spa += __shfl_xor_sync(~0u, spa, o);
            }
            if (lid == 0) {
                p2s[row]  = sp;
                pas[row]  = spa;
                float na  = sqrtf(sa);
                inas[row] = fast_rcp(fmaxf(na, 1e-12f));
                w2s[row]  = 2.0f * na * LN2F;
            }
        }
    }
    // first __syncthreads in the tile loop orders these vs epilogue reads

    u64t axp[4][4] = {};   // packed (even-k, odd-k) partials of x.p
    u64t axa[4][4] = {};   // packed partials of x.a

    for (int k0 = 0; k0 < D_TOT; k0 += 2 * KP) {
        // Tile fill: 1024 float2 per array, 4/thread, coalesced on k.
        #pragma unroll
        for (int r = 0; r < 4; r++) {
            int idx = tid + r * 256;
            int kk  = idx & 15;
            int row = idx >> 4;
            Xs[kk][row] = *(const float2*)&X[(size_t)(n0 + row) * D_TOT + k0 + 2 * kk];
            Ps[kk][row] = *(const float2*)&P[(size_t)(c0 + row) * D_TOT + k0 + 2 * kk];
            As[kk][row] = *(const float2*)&A[(size_t)(c0 + row) * D_TOT + k0 + 2 * kk];
        }
        __syncthreads();

        #pragma unroll
        for (int k = 0; k < KP; k++) {
            // Plain C++ 16B shared loads: each ulonglong2 half is one packed
            // (k_even, k_odd) f32x2 operand. Compiler schedules/pipelines.
            ulonglong2 xv0 = *(const ulonglong2*)&Xs[k][ty * 4];
            ulonglong2 xv1 = *(const ulonglong2*)&Xs[k][ty * 4 + 2];
            ulonglong2 pv0 = *(const ulonglong2*)&Ps[k][tx * 4];
            ulonglong2 pv1 = *(const ulonglong2*)&Ps[k][tx * 4 + 2];
            ulonglong2 av0 = *(const ulonglong2*)&As[k][tx * 4];
            ulonglong2 av1 = *(const ulonglong2*)&As[k][tx * 4 + 2];
            u64t xk[4] = {xv0.x, xv0.y, xv1.x, xv1.y};
            u64t pk[4] = {pv0.x, pv0.y, pv1.x, pv1.y};
            u64t ak[4] = {av0.x, av0.y, av1.x, av1.y};
            #pragma unroll
            for (int i = 0; i < 4; i++)
                #pragma unroll
                for (int j = 0; j < 4; j++) {
                    axp[i][j] = fma2(xk[i], pk[j], axp[i][j]);
                    axa[i][j] = fma2(xk[i], ak[j], axa[i][j]);
                }
        }
        __syncthreads();
    }

    // ---- Epilogue: fused hyperbolic math, 1 rcp + 1 sqrt + 1 lg2 per elem.
    float x2v[4], x2p1[4];
    #pragma unroll
    for (int i = 0; i < 4; i++) {
        x2v[i]  = x2s[ty * 4 + i];
        x2p1[i] = 1.0f + x2v[i];
    }
    float p2v[4], bet[4], bet2[4], pav[4], inav[4], wv[4];
    #pragma unroll
    for (int j = 0; j < 4; j++) {
        p2v[j]  = p2s[tx * 4 + j];
        bet[j]  = 1.0f - p2v[j];
        bet2[j] = bet[j] * bet[j];
        pav[j]  = pas[tx * 4 + j];
        inav[j] = inas[tx * 4 + j];
        wv[j]   = w2s[tx * 4 + j];
    }

    #pragma unroll
    for (int i = 0; i < 4; i++) {
        const int n = n0 + ty * 4 + i;
        float res[4];
        #pragma unroll
        for (int j = 0; j < 4; j++) {
            float xp  = hsum2(axp[i][j]);            // x.p
            float xa  = hsum2(axa[i][j]);            // x.a
            float txy = -2.0f * xp;                  // 2*xy (xy = mp.x = -xp)
            float alpha = x2p1[i] + txy;             // 1 + 2xy + x2
            float den   = fmaf(p2v[j], x2v[i], 1.0f + txy);
            // s = ||res||^2 * den^2 = a^2 p2 + a*b*txy + b^2 x2
            float s   = fmaf(alpha, fmaf(alpha, p2v[j], bet[j] * txy),
                             bet2[j] * x2v[i]);
            float num = fmaf(bet[j], xa, -alpha * pav[j]);   // b*xa - a*pa
            float d2ms = fmaf(den, den, -s);                 // den^2 - s
            // dot*lam = 2*den*num / (na * (den^2 - s))
            float arg = 2.0f * den * num * inav[j] * fast_rcp(d2ms);
            float q   = arg + fast_sqrt(fmaf(arg, arg, 1.0f));
            res[j] = wv[j] * fast_lg2(q);            // 2*na*ln2 * log2(q)
        }
        float4 o = {res[0], res[1], res[2], res[3]};
        *(float4*)&out[(size_t)n * C_TOT + c0 + tx * 4] = o;
    }
}

extern "C" void kernel_launch(void* const* d_in, const int* in_sizes, int n_in,
                              void* d_out, int out_size) {
    const float* X = (const float*)d_in[0];   // output_before (N, D)
    const float* A = (const float*)d_in[1];   // a_mlr (C, D)
    const float* P = (const float*)d_in[2];   // p_mlr (C, D)
    float* out = (float*)d_out;               // (N, C)

    dim3 grid(C_TOT / BC, N_TOT / BN);        // (4, 64) = 256 blocks
    hyp_mlr_kernel<<<grid, 256>>>(X, A, P, out);
}

// round 5
// speedup vs baseline: 1.2918x; 1.2734x over previous
#include <cuda_runtime.h>
#include <math.h>

// Hyp-MLR: N=4096, C=256, D=128, CURV=1
// out[n,c] = 2*||a_c|| * asinh(dot*lam); reduces to two GEMMs (X.P^T, X.A^T)
// + per-row/per-class stats. Scalar-FFMA dual GEMM (R1 structure, proven
// issue=67%), stats hoisted to a shuffle preamble, fused approx epilogue.

#define N_TOT 4096
#define C_TOT 256
#define D_TOT 128
#define BN 64
#define BC 64
#define KT 32
#define PAD 4
#define LN2F 0.69314718055994530942f

__device__ __forceinline__ float fast_rcp(float x) {
    float y; asm("rcp.approx.f32 %0, %1;" : "=f"(y) : "f"(x)); return y;
}
__device__ __forceinline__ float fast_sqrt(float x) {
    float y; asm("sqrt.approx.f32 %0, %1;" : "=f"(y) : "f"(x)); return y;
}
__device__ __forceinline__ float fast_lg2(float x) {
    float y; asm("lg2.approx.f32 %0, %1;" : "=f"(y) : "f"(x)); return y;
}

__global__ __launch_bounds__(256, 2) void hyp_mlr_kernel(
    const float* __restrict__ X,   // (N, D)
    const float* __restrict__ A,   // (C, D)
    const float* __restrict__ P,   // (C, D)
    float* __restrict__ out)       // (N, C)
{
    __shared__ float Xs[KT][BN + PAD];
    __shared__ float Ps[KT][BC + PAD];
    __shared__ float As[KT][BC + PAD];
    __shared__ float x2s[BN];                  // ||x||^2 per row
    __shared__ float p2s[BC], pas[BC];         // ||p||^2, p.a per class
    __shared__ float inas[BC], w2s[BC];        // 1/||a||, 2*||a||*ln2

    const int tid = threadIdx.x;
    const int lid = tid & 31;
    const int wid = tid >> 5;
    const int tx  = tid & 15;   // c dim
    const int ty  = tid >> 4;   // n dim
    const int n0  = blockIdx.y * BN;
    const int c0  = blockIdx.x * BC;

    // ---- Stats preamble: warps 0-3 -> 64 n-rows; warps 4-7 -> 64 c-rows.
    if (wid < 4) {
        #pragma unroll 4
        for (int j = 0; j < 16; j++) {
            int row = wid * 16 + j;
            float4 v = *(const float4*)&X[(size_t)(n0 + row) * D_TOT + lid * 4];
            float s = v.x * v.x + v.y * v.y + v.z * v.z + v.w * v.w;
            #pragma unroll
            for (int o = 16; o > 0; o >>= 1) s += __shfl_xor_sync(~0u, s, o);
            if (lid == 0) x2s[row] = s;
        }
    } else {
        #pragma unroll 4
        for (int j = 0; j < 16; j++) {
            int row = (wid - 4) * 16 + j;
            float4 p = *(const float4*)&P[(size_t)(c0 + row) * D_TOT + lid * 4];
            float4 a = *(const float4*)&A[(size_t)(c0 + row) * D_TOT + lid * 4];
            float sp  = p.x * p.x + p.y * p.y + p.z * p.z + p.w * p.w;
            float sa  = a.x * a.x + a.y * a.y + a.z * a.z + a.w * a.w;
            float spa = p.x * a.x + p.y * a.y + p.z * a.z + p.w * a.w;
            #pragma unroll
            for (int o = 16; o > 0; o >>= 1) {
                sp  += __shfl_xor_sync(~0u, sp,  o);
                sa  += __shfl_xor_sync(~0u, sa,  o);
                spa += __shfl_xor_sync(~0u, spa, o);
            }
            if (lid == 0) {
                p2s[row]  = sp;
                pas[row]  = spa;
                float na  = sqrtf(sa);
                inas[row] = fast_rcp(fmaxf(na, 1e-12f));
                w2s[row]  = 2.0f * na * LN2F;
            }
        }
    }
    // first __syncthreads in the tile loop orders these vs epilogue reads

    float axp[4][4] = {};   // x.p partials
    float axa[4][4] = {};   // x.a partials

    for (int k0 = 0; k0 < D_TOT; k0 += KT) {
        // Cooperative tile load: 64 rows x 32 k per array, coalesced on k.
        #pragma unroll
        for (int r = 0; r < 8; r++) {
            int idx = tid + r * 256;
            int kk  = idx & 31;
            int row = idx >> 5;
            Xs[kk][row] = X[(size_t)(n0 + row) * D_TOT + k0 + kk];
            Ps[kk][row] = P[(size_t)(c0 + row) * D_TOT + k0 + kk];
            As[kk][row] = A[(size_t)(c0 + row) * D_TOT + k0 + kk];
        }
        __syncthreads();

        #pragma unroll
        for (int k = 0; k < KT; k++) {
            float4 xv = *(const float4*)&Xs[k][ty * 4];
            float4 pv = *(const float4*)&Ps[k][tx * 4];
            float4 av = *(const float4*)&As[k][tx * 4];
            float xr[4] = {xv.x, xv.y, xv.z, xv.w};
            float pr[4] = {pv.x, pv.y, pv.z, pv.w};
            float ar[4] = {av.x, av.y, av.z, av.w};
            #pragma unroll
            for (int i = 0; i < 4; i++)
                #pragma unroll
                for (int j = 0; j < 4; j++) {
                    axp[i][j] = fmaf(xr[i], pr[j], axp[i][j]);
                    axa[i][j] = fmaf(xr[i], ar[j], axa[i][j]);
                }
        }
        __syncthreads();
    }

    // ---- Epilogue: fused hyperbolic math, 1 rcp + 1 sqrt + 1 lg2 per elem.
    float x2v[4], x2p1[4];
    #pragma unroll
    for (int i = 0; i < 4; i++) {
        x2v[i]  = x2s[ty * 4 + i];
        x2p1[i] = 1.0f + x2v[i];
    }
    float p2v[4], bet[4], bet2[4], pav[4], inav[4], wv[4];
    #pragma unroll
    for (int j = 0; j < 4; j++) {
        p2v[j]  = p2s[tx * 4 + j];
        bet[j]  = 1.0f - p2v[j];
        bet2[j] = bet[j] * bet[j];
        pav[j]  = pas[tx * 4 + j];
        inav[j] = inas[tx * 4 + j];
        wv[j]   = w2s[tx * 4 + j];
    }

    #pragma unroll
    for (int i = 0; i < 4; i++) {
        const int n = n0 + ty * 4 + i;
        float res[4];
        #pragma unroll
        for (int j = 0; j < 4; j++) {
            float xp  = axp[i][j];                   // x.p
            float xa  = axa[i][j];                   // x.a
            float txy = -2.0f * xp;                  // 2*xy (xy = mp.x = -xp)
            float alpha = x2p1[i] + txy;             // 1 + 2xy + x2
            float den   = fmaf(p2v[j], x2v[i], 1.0f + txy);
            // s = ||res||^2 * den^2 = a^2 p2 + a*b*txy + b^2 x2
            float s   = fmaf(alpha, fmaf(alpha, p2v[j], bet[j] * txy),
                             bet2[j] * x2v[i]);
            float num = fmaf(bet[j], xa, -alpha * pav[j]);   // b*xa - a*pa
            float d2ms = fmaf(den, den, -s);                 // den^2 - s
            // dot*lam = 2*den*num / (na * (den^2 - s))
            float arg = 2.0f * den * num * inav[j] * fast_rcp(d2ms);
            float q   = arg + fast_sqrt(fmaf(arg, arg, 1.0f));
            res[j] = wv[j] * fast_lg2(q);            // 2*na*ln2 * log2(q)
        }
        float4 o = {res[0], res[1], res[2], res[3]};
        *(float4*)&out[(size_t)n * C_TOT + c0 + tx * 4] = o;
    }
}

extern "C" void kernel_launch(void* const* d_in, const int* in_sizes, int n_in,
                              void* d_out, int out_size) {
    const float* X = (const float*)d_in[0];   // output_before (N, D)
    const float* A = (const float*)d_in[1];   // a_mlr (C, D)
    const float* P = (const float*)d_in[2];   // p_mlr (C, D)
    float* out = (float*)d_out;               // (N, C)

    dim3 grid(C_TOT / BC, N_TOT / BN);        // (4, 64) = 256 blocks
    hyp_mlr_kernel<<<grid, 256>>>(X, A, P, out);
}